// round 9
// baseline (speedup 1.0000x reference)
#include <cuda_runtime.h>
#include <cuda_fp16.h>
#include <cuda_bf16.h>

// GNN_26242250178821: 2-layer GCN forward, CSR-gather + fp16 feature rows,
// register-tiled broadcast GEMM, MLP-8 batched gather aggregation.
//
// RULE (root cause of earlier rounds): never pass a __device__ symbol as a
// kernel argument from host code — on GB300/ATS the host-shadow address is
// silently writable. All g_* arrays referenced only inside device code.

#define D 64
#define MAXN 150016
#define MAXE  3000064
#define MAXELEM (150016 * 64)

__device__ int    g_deg[MAXN];
__device__ int    g_off[MAXN + 1];
__device__ int    g_pos[MAXN];
__device__ float  g_dinv[MAXN];
__device__ unsigned long long g_edge[MAXE];  // (coef bits << 32) | src
__device__ __half g_xwh[MAXELEM];            // xw rows in fp16 (128 B/row)
__device__ int    g_idx64;                   // 1 if edge_index is int64

__global__ void k_detect(const unsigned long long* __restrict__ p, int nwords) {
    __shared__ int any;
    if (threadIdx.x == 0) any = 0;
    __syncthreads();
    for (int i = threadIdx.x; i < nwords; i += blockDim.x)
        if ((p[i] >> 32) != 0ull) any = 1;
    __syncthreads();
    if (threadIdx.x == 0) g_idx64 = any ? 0 : 1;
}

__device__ __forceinline__ int load_idx(const void* ei, long long i) {
    if (g_idx64) return (int)((const long long*)ei)[i];
    return ((const int*)ei)[i];
}

__global__ void k_zero_deg(int n) {
    int i = blockIdx.x * blockDim.x + threadIdx.x;
    if (i < n) g_deg[i] = 0;
}

__global__ void k_count_deg(const void* __restrict__ ei, int e, int n) {
    int i = blockIdx.x * blockDim.x + threadIdx.x;
    if (i < e) {
        int c = load_idx(ei, (long long)e + i);   // col half
        if ((unsigned)c < (unsigned)n) atomicAdd(&g_deg[c], 1);
    }
}

__global__ void k_dinv(int n) {
    int i = blockIdx.x * blockDim.x + threadIdx.x;
    if (i < n) g_dinv[i] = rsqrtf((float)g_deg[i] + 1.0f);
}

// Single-block (1024 threads) exclusive scan of g_deg into g_off and g_pos.
__global__ void k_scan(int n) {
    __shared__ int warp_sums[32];
    int tid = threadIdx.x;
    int chunk = (n + 1023) / 1024;
    int start = tid * chunk;
    int end = start + chunk; if (end > n) end = n;
    int s = 0;
    for (int i = start; i < end; i++) s += g_deg[i];

    int lane = tid & 31, wid = tid >> 5;
    int v = s;
    #pragma unroll
    for (int o = 1; o < 32; o <<= 1) {
        int t = __shfl_up_sync(~0u, v, o);
        if (lane >= o) v += t;
    }
    if (lane == 31) warp_sums[wid] = v;
    __syncthreads();
    if (wid == 0) {
        int w = warp_sums[lane];
        #pragma unroll
        for (int o = 1; o < 32; o <<= 1) {
            int t = __shfl_up_sync(~0u, w, o);
            if (lane >= o) w += t;
        }
        warp_sums[lane] = w;
    }
    __syncthreads();
    int excl = v - s + (wid > 0 ? warp_sums[wid - 1] : 0);

    int run = excl;
    for (int i = start; i < end; i++) {
        g_off[i] = run;
        g_pos[i] = run;
        run += g_deg[i];
    }
    if (tid == 1023) g_off[n] = run;
}

// Bucket edges: one scattered 8-byte store per edge.
__global__ void k_build(const void* __restrict__ ei, int e, int n) {
    int i = blockIdx.x * blockDim.x + threadIdx.x;
    if (i < e) {
        int r = load_idx(ei, i);
        int c = load_idx(ei, (long long)e + i);
        if ((unsigned)r < (unsigned)n && (unsigned)c < (unsigned)n) {
            int p = atomicAdd(&g_pos[c], 1);
            float cf = g_dinv[r] * g_dinv[c];
            g_edge[p] = ((unsigned long long)__float_as_uint(cf) << 32)
                        | (unsigned)r;
        }
    }
}

// layer0 = concat(users, items) as float4
__global__ void k_concat(const float4* __restrict__ u, const float4* __restrict__ it,
                         float4* __restrict__ out0, int nu4, int tot4) {
    int i = blockIdx.x * blockDim.x + threadIdx.x;
    if (i < tot4) out0[i] = (i < nu4) ? u[i] : it[i - nu4];
}

// Register-tiled GEMM: g_xwh[n,64] = fp16( relu?(x)[n,64] @ W[64,64] ).
__global__ void __launch_bounds__(256) k_gemm64(
        const float* __restrict__ x, const float* __restrict__ W,
        int n, int relu_in) {
    __shared__ float Ws[64 * 64];
    __shared__ float xs[128 * 64];
    int tid = threadIdx.x;
    int row0 = blockIdx.x * 128;
    int nr = n - row0; if (nr > 128) nr = 128;

    for (int i = tid; i < 4096; i += 256) Ws[i] = W[i];
    {
        const float4* x4 = (const float4*)(x + (size_t)row0 * 64);
        float4* xs4 = (float4*)xs;
        int tot4 = nr * 16;
        for (int i = tid; i < tot4; i += 256) {
            float4 v = x4[i];
            if (relu_in) {
                v.x = fmaxf(v.x, 0.0f); v.y = fmaxf(v.y, 0.0f);
                v.z = fmaxf(v.z, 0.0f); v.w = fmaxf(v.w, 0.0f);
            }
            xs4[i] = v;
        }
        for (int i = nr * 16 + tid; i < 128 * 16; i += 256)
            xs4[i] = make_float4(0.f, 0.f, 0.f, 0.f);
    }
    __syncthreads();

    int warp = tid >> 5, lane = tid & 31;
    int rbase = warp * 16;

    float acc0[16], acc1[16];
    #pragma unroll
    for (int r = 0; r < 16; r++) { acc0[r] = 0.0f; acc1[r] = 0.0f; }

    #pragma unroll 8
    for (int k = 0; k < 64; k++) {
        float w0 = Ws[k * 64 + lane];
        float w1 = Ws[k * 64 + lane + 32];
        #pragma unroll
        for (int r = 0; r < 16; r++) {
            float xv = xs[(rbase + r) * 64 + k];   // warp broadcast
            acc0[r] += xv * w0;
            acc1[r] += xv * w1;
        }
    }

    #pragma unroll
    for (int r = 0; r < 16; r++) {
        int row = rbase + r;
        if (row < nr) {
            size_t base = (size_t)(row0 + row) * 64;
            g_xwh[base + lane]      = __float2half(acc0[r]);
            g_xwh[base + lane + 32] = __float2half(acc1[r]);
        }
    }
}

// Warp per node; lane owns dims {2*lane, 2*lane+1} -> one coalesced 128B row
// load per edge. Edges processed in batches of 8 independent gathers (MLP=8):
// extract 8 (src,coef) via shuffle, issue 8 __ldg, then accumulate.
__global__ void k_agg(const float* __restrict__ b, float* __restrict__ out, int n) {
    int node = (blockIdx.x * blockDim.x + threadIdx.x) >> 5;
    int lane = threadIdx.x & 31;
    if (node >= n) return;

    int p0 = g_off[node];
    int p1 = g_off[node + 1];
    float acc0 = 0.0f, acc1 = 0.0f;

    const __half2* xw2 = (const __half2*)g_xwh;

    int p = p0;
    while (p < p1) {
        int cnt = p1 - p; if (cnt > 32) cnt = 32;
        unsigned long long meta = 0;
        if (p + lane < p1) meta = __ldg(&g_edge[p + lane]);

        int j = 0;
        for (; j + 8 <= cnt; j += 8) {
            __half2 h[8]; float cf[8];
            #pragma unroll
            for (int t = 0; t < 8; t++) {
                unsigned long long m = __shfl_sync(~0u, meta, j + t);
                int r = (int)(unsigned)m;
                cf[t] = __uint_as_float((unsigned)(m >> 32));
                h[t] = __ldg(&xw2[(size_t)r * 32 + lane]);
            }
            #pragma unroll
            for (int t = 0; t < 8; t++) {
                float2 f = __half22float2(h[t]);
                acc0 += f.x * cf[t];
                acc1 += f.y * cf[t];
            }
        }
        for (; j < cnt; j++) {
            unsigned long long m = __shfl_sync(~0u, meta, j);
            int r = (int)(unsigned)m;
            float cf = __uint_as_float((unsigned)(m >> 32));
            float2 f = __half22float2(__ldg(&xw2[(size_t)r * 32 + lane]));
            acc0 += f.x * cf;
            acc1 += f.y * cf;
        }
        p += cnt;
    }

    float di = g_dinv[node];
    float d2 = di * di;
    float2 fs = __half22float2(xw2[(size_t)node * 32 + lane]);
    float2 bb = ((const float2*)b)[lane];
    float2 o;
    o.x = acc0 + fs.x * d2 + bb.x;
    o.y = acc1 + fs.y * d2 + bb.y;
    ((float2*)out)[(size_t)node * 32 + lane] = o;
}

extern "C" void kernel_launch(void* const* d_in, const int* in_sizes, int n_in,
                              void* d_out, int out_size) {
    const float* emb_users = (const float*)d_in[0];
    const float* emb_items = (const float*)d_in[1];
    const float* W1 = (const float*)d_in[2];
    const float* b1 = (const float*)d_in[3];
    const float* W2 = (const float*)d_in[4];
    const float* b2 = (const float*)d_in[5];
    const void*  ei = d_in[6];

    int NU = in_sizes[0] / D;
    int NI = in_sizes[1] / D;
    int N  = NU + NI;
    int E  = in_sizes[6] / 2;

    float* out0 = (float*)d_out;
    float* out1 = out0 + (size_t)N * D;
    float* out2 = out1 + (size_t)N * D;

    const int T = 256;
    int gN = (N + T - 1) / T;
    int gE = (E + T - 1) / T;
    int gW = (int)(((long long)N * 32 + T - 1) / T);   // warp per node

    // Position-4 launch = k_gemm64 (ncu capture target).
    k_detect<<<1, 256>>>((const unsigned long long*)ei, 256);
    k_zero_deg<<<gN, T>>>(N);

    int nu4 = NU * (D / 4), tot4 = N * (D / 4);
    k_concat<<<(tot4 + T - 1) / T, T>>>((const float4*)emb_users,
                                        (const float4*)emb_items,
                                        (float4*)out0, nu4, tot4);

    k_gemm64<<<(N + 127) / 128, T>>>(out0, W1, N, 0);   // capture target

    k_count_deg<<<gE, T>>>(ei, E, N);
    k_dinv<<<gN, T>>>(N);
    k_scan<<<1, 1024>>>(N);
    k_build<<<gE, T>>>(ei, E, N);

    // layer 1 aggregation
    k_agg<<<gW, T>>>(b1, out1, N);

    // layer 2 (relu applied on read of out1)
    k_gemm64<<<(N + 127) / 128, T>>>(out1, W2, N, 1);
    k_agg<<<gW, T>>>(b2, out2, N);
}